// round 10
// baseline (speedup 1.0000x reference)
#include <cuda_runtime.h>
#include <cuda_fp16.h>
#include <cstdint>

#define Bn 256
#define Sn 512
#define Kn 32
#define Fn 64
#define H1n 512
#define H2n 256

// ---------------- device scratch (allocation-free rule) ----------------
__device__ float    g_c1[Sn * H1n];
__device__ unsigned g_m[Bn * H2n];
__device__ __half   g_w1t[H1n * 2048];     // [n][k], k = nb*64+f
__device__ __half   g_w2t[H2n * H1n];      // [n2][h1]
__device__ __half   g_xr[Bn * Sn * Fn];
__device__ unsigned g_done;

// ---------------- smem layout (bytes) ----------------
// GEMM1 stage: A (128 rows x 32 halves, 80B stride) + B (256 rows x 32 halves).
// 80B = 20 words (== 20 mod 32): 8-row LDSM phases conflict-free.
#define AROWB 80u
#define A_TILE (128u * AROWB)        // 10240
#define B_TILE (256u * AROWB)        // 20480
#define STGB   (A_TILE + B_TILE)     // 30720 per stage, 2 stages
#define HS_B   (2u * STGB)           // 61440
#define HROWB  1040u                 // 512 halves (1024B) + 16B pad; 260w==4 mod 32
#define SMEM_BYTES (61440 + 128 * 1040)   // 194560

// ---------------- PTX helpers ----------------
__device__ __forceinline__ uint32_t smem_u32(const void* p) {
    uint32_t a;
    asm("{ .reg .u64 t; cvta.to.shared.u64 t, %1; cvt.u32.u64 %0, t; }" : "=r"(a) : "l"(p));
    return a;
}
__device__ __forceinline__ void cpasync16(uint32_t s, const void* g) {
    asm volatile("cp.async.cg.shared.global [%0], [%1], 16;" :: "r"(s), "l"(g));
}
#define CP_COMMIT() asm volatile("cp.async.commit_group;")
#define CP_WAIT0()  asm volatile("cp.async.wait_group 0;")

#define LDSM4(r0, r1, r2, r3, addr) \
    asm volatile("ldmatrix.sync.aligned.m8n8.x4.shared.b16 {%0,%1,%2,%3}, [%4];" \
        : "=r"(r0), "=r"(r1), "=r"(r2), "=r"(r3) : "r"(addr))

__device__ __forceinline__ void mma16(float* d, const uint32_t* a,
                                      uint32_t b0, uint32_t b1) {
    asm volatile(
        "mma.sync.aligned.m16n8k16.row.col.f32.f16.f16.f32 "
        "{%0,%1,%2,%3}, {%4,%5,%6,%7}, {%8,%9}, {%0,%1,%2,%3};"
        : "+f"(d[0]), "+f"(d[1]), "+f"(d[2]), "+f"(d[3])
        : "r"(a[0]), "r"(a[1]), "r"(a[2]), "r"(a[3]), "r"(b0), "r"(b1));
}

// ---------------- merged prep kernel ----------------
#define PREP_BLOCKS 38144
__global__ void prep_all_kernel(const float* __restrict__ x,
                                const float* __restrict__ W1,
                                const float* __restrict__ b1,
                                const float* __restrict__ W2,
                                const float* __restrict__ dist) {
    const int blk = blockIdx.x, t = threadIdx.x;
    if (blk < 32768) {
        int i = blk * 256 + t;
        g_xr[i] = __float2half_rn(x[i]);
    } else if (blk < 36864) {
        int idx = (blk - 32768) * 256 + t;
        int k = idx & 2047, n = idx >> 11;
        int row = (k >> 6) * 65 + (k & 63);
        g_w1t[(size_t)n * 2048 + k] = __float2half_rn(W1[(size_t)row * H1n + n]);
    } else if (blk < 37376) {
        int idx = (blk - 36864) * 256 + t;
        int h = idx & 511, n = idx >> 9;
        g_w2t[(size_t)n * H1n + h] = __float2half_rn(W2[(size_t)h * H2n + n]);
    } else if (blk < 37888) {
        int s = blk - 37376;
#pragma unroll
        for (int hh = 0; hh < 2; hh++) {
            int h = t + hh * 256;
            float acc = b1[h];
#pragma unroll
            for (int k = 0; k < Kn; k++)
                acc = fmaf(dist[s * Kn + k], W1[(k * 65 + 64) * H1n + h], acc);
            g_c1[s * H1n + h] = acc;
        }
    } else {
        int i = (blk - 37888) * 256 + t;
        g_m[i] = 0u;
        if (blk == 37888 && t == 0) g_done = 0u;
    }
}

// ---------------- load helpers (256 threads) ----------------
// GEMM1 chunk c (k = c*32..+32): neighbor c>>1, f-half c&1.
// A: 128 rows x 64B (2 ops/thread). B: W1t rows [n1*256..+256) x 64B (4 ops/thread).
__device__ __forceinline__ void issue_g1(int c, int n1, int st, int tid,
                                         uint32_t smb, const int* __restrict__ nbh_s,
                                         int b0) {
    const int sidx = __ldg(&nbh_s[c >> 1]);
    const int f0 = (c & 1) * 32;
    const uint32_t ab = smb + (uint32_t)st * STGB;
    const __half* asrc = g_xr + ((size_t)b0 * Sn + sidx) * Fn + f0;
#pragma unroll
    for (int p = 0; p < 2; p++) {
        int u = tid + p * 256; int r = u >> 2, q = u & 3;
        cpasync16(ab + (uint32_t)r * AROWB + (uint32_t)q * 16u,
                  asrc + (size_t)r * (Sn * Fn) + q * 8);
    }
    const uint32_t bb = ab + A_TILE;
    const __half* bsrc = g_w1t + (size_t)(n1 * 256) * 2048 + c * 32;
#pragma unroll
    for (int p = 0; p < 4; p++) {
        int u = tid + p * 256; int r = u >> 2, q = u & 3;
        cpasync16(bb + (uint32_t)r * AROWB + (uint32_t)q * 16u,
                  bsrc + (size_t)r * 2048 + q * 8);
    }
}
// W2 chunk kc (k = kc*32..+32): 256 rows x 64B into stage's B region.
__device__ __forceinline__ void issue_g2(int kc, int st, int tid, uint32_t smb) {
    const uint32_t bb = smb + (uint32_t)st * STGB + A_TILE;
    const __half* bsrc = g_w2t + kc * 32;
#pragma unroll
    for (int p = 0; p < 4; p++) {
        int u = tid + p * 256; int r = u >> 2, q = u & 3;
        cpasync16(bb + (uint32_t)r * AROWB + (uint32_t)q * 16u,
                  bsrc + (size_t)r * H1n + q * 8);
    }
}

// ---------------- fused fp16 mma kernel (+ inline finalize) ----------------
__global__ __launch_bounds__(256, 1)
void fused_mma_kernel(const int* __restrict__ nbh, const float* __restrict__ b2,
                      const float* __restrict__ Wd, const float* __restrict__ bd,
                      float* __restrict__ out) {
    extern __shared__ char smc[];
    const int tid = threadIdx.x, lane = tid & 31, wid = tid >> 5;
    const int gid = lane >> 2, tig = lane & 3;
    const int wm  = (wid >> 2) * 64;    // warp M offset (0 or 64)
    const int wnc = wid & 3;            // warp N col (0..3), 64 each
    const int s = blockIdx.y, b0 = blockIdx.x * 128;
    const int* nbh_s = nbh + s * Kn;
    const uint32_t smb = smem_u32(smc);

    // ldmatrix lane addressing (16-row x4 tiles)
    const uint32_t a_lrow = (uint32_t)(lane & 15) * AROWB + (uint32_t)(lane >> 4) * 16u;
    const int bg = lane >> 3;
    const uint32_t b_lrow = (uint32_t)(((bg >> 1) * 8) + (lane & 7)) * AROWB
                          + (uint32_t)(bg & 1) * 16u;
    const uint32_t h_lrow = (uint32_t)(lane & 15) * HROWB + (uint32_t)(lane >> 4) * 16u;

    // ================= Phase 1: h1 = relu(gather @ W1 + c1) -> Hs =================
    for (int n1 = 0; n1 < 2; n1++) {
        float acc1[4][8][4];
#pragma unroll
        for (int mt = 0; mt < 4; mt++)
#pragma unroll
            for (int nt = 0; nt < 8; nt++)
#pragma unroll
                for (int i = 0; i < 4; i++) acc1[mt][nt][i] = 0.f;

        if (n1 == 0) { issue_g1(0, 0, 0, tid, smb, nbh_s, b0); CP_COMMIT(); }

        for (int c = 0; c < 64; c++) {
            CP_WAIT0();
            __syncthreads();
            if (c + 1 < 64) { issue_g1(c + 1, n1, (c + 1) & 1, tid, smb, nbh_s, b0); CP_COMMIT(); }

            const uint32_t stb = smb + (uint32_t)(c & 1) * STGB;
            const uint32_t aT = stb + (uint32_t)wm * AROWB + a_lrow;
            const uint32_t bT = stb + A_TILE + (uint32_t)(wnc * 64) * AROWB + b_lrow;
#pragma unroll
            for (int ks = 0; ks < 2; ks++) {
                uint32_t a[4][4];
#pragma unroll
                for (int mt = 0; mt < 4; mt++)
                    LDSM4(a[mt][0], a[mt][1], a[mt][2], a[mt][3],
                          aT + (uint32_t)mt * (16 * AROWB) + ks * 32);
#pragma unroll
                for (int j = 0; j < 4; j++) {
                    uint32_t r0, r1, r2, r3;
                    LDSM4(r0, r1, r2, r3, bT + (uint32_t)j * (16 * AROWB) + ks * 32);
#pragma unroll
                    for (int mt = 0; mt < 4; mt++) {
                        mma16(acc1[mt][2 * j],     a[mt], r0, r1);
                        mma16(acc1[mt][2 * j + 1], a[mt], r2, r3);
                    }
                }
            }
        }

        // tail prefetch (stage0 free: last read c=62, all passed c=63 sync)
        if (n1 == 0) issue_g1(0, 1, 0, tid, smb, nbh_s, b0);
        else         issue_g2(0, 0, tid, smb);
        CP_COMMIT();

        // epilogue: relu(acc1 + c1) -> fp16 -> Hs columns [n1*256..+256)
        const float* c1p = g_c1 + s * H1n + n1 * 256;
#pragma unroll
        for (int nt = 0; nt < 8; nt++) {
            const int col = wnc * 64 + nt * 8 + tig * 2;
            const float2 cv = __ldg((const float2*)(c1p + col));
            const uint32_t colb = (uint32_t)(n1 * 256 + col) * 2u;
#pragma unroll
            for (int mt = 0; mt < 4; mt++) {
                const int r = wm + mt * 16 + gid;
                __half2* h0  = (__half2*)(smc + HS_B + (uint32_t)r * HROWB + colb);
                __half2* h1r = (__half2*)(smc + HS_B + (uint32_t)(r + 8) * HROWB + colb);
                *h0  = __floats2half2_rn(fmaxf(acc1[mt][nt][0] + cv.x, 0.f),
                                         fmaxf(acc1[mt][nt][1] + cv.y, 0.f));
                *h1r = __floats2half2_rn(fmaxf(acc1[mt][nt][2] + cv.x, 0.f),
                                         fmaxf(acc1[mt][nt][3] + cv.y, 0.f));
            }
        }
    }

    // ================= Phase 2: h2 = Hs @ W2t^T, k = 512 in 16 chunks =================
    float acc2[4][8][4];
#pragma unroll
    for (int mt = 0; mt < 4; mt++)
#pragma unroll
        for (int nt = 0; nt < 8; nt++)
#pragma unroll
            for (int i = 0; i < 4; i++) acc2[mt][nt][i] = 0.f;

    for (int kc = 0; kc < 16; kc++) {
        CP_WAIT0();
        __syncthreads();   // W2 chunk visible; kc=0 also fences all Hs writes
        if (kc + 1 < 16) { issue_g2(kc + 1, (kc + 1) & 1, tid, smb); CP_COMMIT(); }

        const uint32_t aT = smb + HS_B + (uint32_t)wm * HROWB + h_lrow + (uint32_t)kc * 64u;
        const uint32_t bT = smb + (uint32_t)(kc & 1) * STGB + A_TILE
                          + (uint32_t)(wnc * 64) * AROWB + b_lrow;
#pragma unroll
        for (int ks = 0; ks < 2; ks++) {
            uint32_t a[4][4];
#pragma unroll
            for (int mt = 0; mt < 4; mt++)
                LDSM4(a[mt][0], a[mt][1], a[mt][2], a[mt][3],
                      aT + (uint32_t)mt * (16 * HROWB) + ks * 32);
#pragma unroll
            for (int j = 0; j < 4; j++) {
                uint32_t r0, r1, r2, r3;
                LDSM4(r0, r1, r2, r3, bT + (uint32_t)j * (16 * AROWB) + ks * 32);
#pragma unroll
                for (int mt = 0; mt < 4; mt++) {
                    mma16(acc2[mt][2 * j],     a[mt], r0, r1);
                    mma16(acc2[mt][2 * j + 1], a[mt], r2, r3);
                }
            }
        }
    }

    // -------- epilogue: relu(acc2 + b2) -> atomicMax --------
#pragma unroll
    for (int nt = 0; nt < 8; nt++) {
        const int n2 = wnc * 64 + nt * 8 + tig * 2;
        const float2 bv = __ldg((const float2*)(b2 + n2));
#pragma unroll
        for (int mt = 0; mt < 4; mt++) {
            const int r = b0 + wm + mt * 16 + gid;
            float v0 = fmaxf(acc2[mt][nt][0] + bv.x, 0.f);
            float v1 = fmaxf(acc2[mt][nt][1] + bv.y, 0.f);
            float v2 = fmaxf(acc2[mt][nt][2] + bv.x, 0.f);
            float v3 = fmaxf(acc2[mt][nt][3] + bv.y, 0.f);
            atomicMax(&g_m[r * H2n + n2],           __float_as_uint(v0));
            atomicMax(&g_m[r * H2n + n2 + 1],       __float_as_uint(v1));
            atomicMax(&g_m[(r + 8) * H2n + n2],     __float_as_uint(v2));
            atomicMax(&g_m[(r + 8) * H2n + n2 + 1], __float_as_uint(v3));
        }
    }

    // -------- inline finalize --------
    __threadfence();
    __shared__ unsigned s_last;
    if (tid == 0) {
        unsigned v = atomicAdd(&g_done, 1u);
        s_last = (v == 1023u) ? 1u : 0u;
    }
    __syncthreads();
    if (s_last) {
        const float bdv = __ldg(&bd[0]);
        for (int bb = 0; bb < 32; bb++) {
            const int b = wid * 32 + bb;
            float acc = 0.f;
#pragma unroll
            for (int q = 0; q < 8; q++) {
                const int n = q * 32 + lane;
                acc += __uint_as_float(__ldcg(&g_m[b * H2n + n])) * __ldg(&Wd[n]);
            }
#pragma unroll
            for (int off = 16; off; off >>= 1)
                acc += __shfl_xor_sync(0xFFFFFFFFu, acc, off);
            if (lane == 0) out[b] = acc + bdv;
        }
    }
}

extern "C" void kernel_launch(void* const* d_in, const int* in_sizes, int n_in,
                              void* d_out, int out_size) {
    const float* x    = (const float*)d_in[0];
    const int*   nbh  = (const int*)  d_in[1];
    const float* dist = (const float*)d_in[2];
    const float* W1   = (const float*)d_in[3];
    const float* b1   = (const float*)d_in[4];
    const float* W2   = (const float*)d_in[5];
    const float* b2   = (const float*)d_in[6];
    const float* Wd   = (const float*)d_in[7];
    const float* bd   = (const float*)d_in[8];
    float* out = (float*)d_out;

    static bool attr_set = false;
    if (!attr_set) {
        cudaFuncSetAttribute(fused_mma_kernel,
                             cudaFuncAttributeMaxDynamicSharedMemorySize, SMEM_BYTES);
        attr_set = true;
    }

    prep_all_kernel<<<PREP_BLOCKS, 256>>>(x, W1, b1, W2, dist);
    fused_mma_kernel<<<dim3(2, Sn), 256, SMEM_BYTES>>>(nbh, b2, Wd, bd, out);
}